// round 6
// baseline (speedup 1.0000x reference)
#include <cuda_runtime.h>
#include <cuda_fp16.h>
#include <mma.h>

using namespace nvcuda;

static constexpr int   T = 262144;
static constexpr int   S = 128;
static constexpr int   H = 1024;
static constexpr int   A = 16;
static constexpr float GAMMA = 0.99f;
static constexpr float EPSC  = 0.2f;
static constexpr float LOG_SQRT_2PI = 0.91893853320467274178f;

// ---------------- scratch (no allocation allowed) ----------------
__device__ float g_adv[T];
__device__ float g_blockA[256];
__device__ float g_blockB[256];
__device__ float g_blockInc[256];
__device__ float g_s1, g_s2, g_actor;
__device__ float g_mean, g_inv, g_critic;

// ---------------- small helpers ----------------
__device__ __forceinline__ float tanh_fast(float x) {
    float y;
    asm("tanh.approx.f32 %0, %1;" : "=f"(y) : "f"(x));
    return y;
}

__device__ __forceinline__ float block_reduce_256(float v, float* red8) {
    #pragma unroll
    for (int o = 16; o > 0; o >>= 1) v += __shfl_down_sync(0xffffffffu, v, o);
    if ((threadIdx.x & 31) == 0) red8[threadIdx.x >> 5] = v;
    __syncthreads();
    if (threadIdx.x < 8) {
        v = red8[threadIdx.x];
        #pragma unroll
        for (int o = 4; o > 0; o >>= 1) v += __shfl_down_sync(0xffu, v, o);
    }
    return v;  // valid in thread 0
}

// ---------------- K0: zero accumulators ----------------
__global__ void k_zero() { g_s1 = 0.f; g_s2 = 0.f; g_actor = 0.f; }

// ---------------- K1: per-block affine composition of the reversed scan ----------------
// ret[i] = r[i] + (gamma*m[i]) * ret[i+1]; block transform x -> A*x + B
__global__ void k_scan1(const float* __restrict__ rewards, const int* __restrict__ masks) {
    int blk = blockIdx.x, tid = threadIdx.x;
    int base = blk * 1024 + tid * 4;
    float4 r = *(const float4*)(rewards + base);
    int4   m = *(const int4*)(masks + base);
    float a = 1.f, b = 0.f, c;
    c = GAMMA * (float)m.w; b = r.w + c * b; a *= c;
    c = GAMMA * (float)m.z; b = r.z + c * b; a *= c;
    c = GAMMA * (float)m.y; b = r.y + c * b; a *= c;
    c = GAMMA * (float)m.x; b = r.x + c * b; a *= c;
    __shared__ float sa[256], sb[256];
    sa[tid] = a; sb[tid] = b;
    __syncthreads();
    if (tid == 0) {
        float Ab = 1.f, Bb = 0.f;
        for (int t = 255; t >= 0; --t) { Bb = sb[t] + sa[t] * Bb; Ab = sa[t] * Ab; }
        g_blockA[blk] = Ab; g_blockB[blk] = Bb;
    }
}

// ---------------- K2: scan the 256 block summaries (right to left) ----------------
__global__ void k_scan2() {
    __shared__ float sa[256], sb[256], sinc[256];
    int tid = threadIdx.x;
    sa[tid] = g_blockA[tid]; sb[tid] = g_blockB[tid];
    __syncthreads();
    if (tid == 0) {
        float x = 0.f;
        for (int b = 255; b >= 0; --b) { sinc[b] = x; x = sb[b] + sa[b] * x; }
    }
    __syncthreads();
    g_blockInc[tid] = sinc[tid];
}

// ---------------- K3: apply scan, compute adv, accumulate sums ----------------
__global__ void k_scan3(const float* __restrict__ rewards, const int* __restrict__ masks,
                        const float* __restrict__ values) {
    int blk = blockIdx.x, tid = threadIdx.x;
    int base = blk * 1024 + tid * 4;
    float4 r = *(const float4*)(rewards + base);
    int4   m = *(const int4*)(masks + base);
    float c0 = GAMMA * (float)m.x, c1 = GAMMA * (float)m.y;
    float c2 = GAMMA * (float)m.z, c3 = GAMMA * (float)m.w;
    float a = 1.f, b = 0.f;
    b = r.w + c3 * b; a *= c3;
    b = r.z + c2 * b; a *= c2;
    b = r.y + c1 * b; a *= c1;
    b = r.x + c0 * b; a *= c0;
    __shared__ float sa[256], sb[256], sinc[256];
    __shared__ float red8[8];
    sa[tid] = a; sb[tid] = b;
    __syncthreads();
    if (tid == 0) {
        float x = g_blockInc[blk];
        for (int t = 255; t >= 0; --t) { sinc[t] = x; x = sb[t] + sa[t] * x; }
    }
    __syncthreads();
    float x = sinc[tid];
    float ret3 = r.w + c3 * x;
    float ret2 = r.z + c2 * ret3;
    float ret1 = r.y + c1 * ret2;
    float ret0 = r.x + c0 * ret1;
    float4 v = *(const float4*)(values + base);
    float4 adv = make_float4(ret0 - v.x, ret1 - v.y, ret2 - v.z, ret3 - v.w);
    *(float4*)(g_adv + base) = adv;
    float s1 = adv.x + adv.y + adv.z + adv.w;
    float s2 = adv.x * adv.x + adv.y * adv.y + adv.z * adv.z + adv.w * adv.w;
    float t1 = block_reduce_256(s1, red8);
    __syncthreads();
    float t2 = block_reduce_256(s2, red8);
    if (tid == 0) { atomicAdd(&g_s1, t1); atomicAdd(&g_s2, t2); }
}

// ---------------- K4: stats ----------------
__global__ void k_stats() {
    float s1 = g_s1, s2 = g_s2;
    float mean = s1 / (float)T;
    float var  = (s2 - s1 * mean) / (float)(T - 1);
    g_mean = mean;
    g_inv  = 1.f / (sqrtf(var) + 1e-7f);
    g_critic = s2 / (float)T;
}

// ---------------- K5: fused policy-net + PPO actor loss ----------------
static constexpr int RT = 256;       // rows per CTA tile
static constexpr int NH = 64;        // H chunk
static constexpr int NCHUNK = H / NH;
static constexpr int LDA = 136;      // half elems
static constexpr int LDW = 72;
static constexpr int LDP = 72;
static constexpr int LDMU = 20;      // float elems (reduces epilogue bank conflicts)

static constexpr int SM_A   = 0;
static constexpr int SM_W1  = SM_A   + RT * LDA * 2;       // 69632
static constexpr int SM_P   = SM_W1  + 128 * LDW * 2;      // 88064
static constexpr int SM_TMP = SM_P   + RT * LDP * 2;       // 124928
static constexpr int SM_WMU = SM_TMP + 8 * 256 * 4;        // 133120
static constexpr int SM_WLV = SM_WMU + 64 * 16 * 2;        // 135168
static constexpr int SM_B1  = SM_WLV + 64 * 16 * 2;        // 137216
static constexpr int SM_TOTAL = SM_B1 + 64 * 4;            // 137472

__global__ __launch_bounds__(256, 1)
void k_main(const float* __restrict__ states, const float* __restrict__ actions,
            const float* __restrict__ blp,
            const float* __restrict__ W1, const float* __restrict__ b1,
            const float* __restrict__ Wmu, const float* __restrict__ bmu,
            const float* __restrict__ Wlv, const float* __restrict__ blv) {
    extern __shared__ char smem[];
    half*  sA   = (half*)(smem + SM_A);
    half*  sW1  = (half*)(smem + SM_W1);
    half*  sP   = (half*)(smem + SM_P);
    float* sTmp = (float*)(smem + SM_TMP);
    half*  sWmu = (half*)(smem + SM_WMU);
    half*  sWlv = (half*)(smem + SM_WLV);
    float* sB1  = (float*)(smem + SM_B1);
    float* sMu  = (float*)(smem + SM_A);        // overlays sA after chunk loop
    float* sLv  = sMu + RT * LDMU;
    __shared__ float red8[8];

    int tid  = threadIdx.x;
    int warp = tid >> 5, lane = tid & 31;
    int r0   = blockIdx.x * RT;

    // load states tile [256 x 128] -> fp16
    #pragma unroll
    for (int it = 0; it < 32; ++it) {
        int idx = tid + 256 * it;           // 8192 float4
        int row = idx >> 5;                 // 32 float4 per row
        int c4  = idx & 31;
        float4 v = *(const float4*)(states + (size_t)(r0 + row) * S + c4 * 4);
        half2* dst = (half2*)(sA + row * LDA + c4 * 4);
        dst[0] = __floats2half2_rn(v.x, v.y);
        dst[1] = __floats2half2_rn(v.z, v.w);
    }

    wmma::fragment<wmma::accumulator, 16, 16, 16, float> accMu[2], accLv[2];
    wmma::fill_fragment(accMu[0], 0.f); wmma::fill_fragment(accMu[1], 0.f);
    wmma::fill_fragment(accLv[0], 0.f); wmma::fill_fragment(accLv[1], 0.f);

    for (int ch = 0; ch < NCHUNK; ++ch) {
        __syncthreads();   // protect sW1/sWmu/sWlv from previous-iteration readers
        // W1 chunk [128 x 64] -> fp16
        #pragma unroll
        for (int it = 0; it < 8; ++it) {
            int idx = tid + 256 * it;       // 2048 float4
            int row = idx >> 4;
            int c4  = idx & 15;
            float4 v = *(const float4*)(W1 + (size_t)row * H + ch * NH + c4 * 4);
            half2* dst = (half2*)(sW1 + row * LDW + c4 * 4);
            dst[0] = __floats2half2_rn(v.x, v.y);
            dst[1] = __floats2half2_rn(v.z, v.w);
        }
        // W_mu / W_lv chunks [64 x 16]
        {
            int row = tid >> 2, c4 = tid & 3;
            float4 v = *(const float4*)(Wmu + (size_t)(ch * NH + row) * A + c4 * 4);
            half2* dm = (half2*)(sWmu + row * 16 + c4 * 4);
            dm[0] = __floats2half2_rn(v.x, v.y);
            dm[1] = __floats2half2_rn(v.z, v.w);
            float4 u = *(const float4*)(Wlv + (size_t)(ch * NH + row) * A + c4 * 4);
            half2* dl = (half2*)(sWlv + row * 16 + c4 * 4);
            dl[0] = __floats2half2_rn(u.x, u.y);
            dl[1] = __floats2half2_rn(u.z, u.w);
        }
        if (tid < 64) sB1[tid] = b1[ch * NH + tid];
        __syncthreads();

        // GEMM1: P = tanh(states @ W1chunk + b1chunk)  [256 x 64]
        #pragma unroll
        for (int j = 0; j < 8; ++j) {
            int tt = warp + 8 * j;
            int tr = tt & 15, tc = tt >> 4;
            wmma::fragment<wmma::accumulator, 16, 16, 16, float> acc;
            wmma::fill_fragment(acc, 0.f);
            #pragma unroll
            for (int k = 0; k < 8; ++k) {
                wmma::fragment<wmma::matrix_a, 16, 16, 16, half, wmma::row_major> fa;
                wmma::fragment<wmma::matrix_b, 16, 16, 16, half, wmma::row_major> fb;
                wmma::load_matrix_sync(fa, sA + tr * 16 * LDA + k * 16, LDA);
                wmma::load_matrix_sync(fb, sW1 + k * 16 * LDW + tc * 16, LDW);
                wmma::mma_sync(acc, fa, fb, acc);
            }
            wmma::store_matrix_sync(sTmp + warp * 256, acc, 16, wmma::mem_row_major);
            __syncwarp();
            #pragma unroll
            for (int i = 0; i < 8; ++i) {
                int pos = lane + 32 * i;
                int rr = pos >> 4, cc = pos & 15;
                float v = sTmp[warp * 256 + pos] + sB1[tc * 16 + cc];
                sP[(tr * 16 + rr) * LDP + tc * 16 + cc] = __float2half_rn(tanh_fast(v));
            }
            __syncwarp();
        }
        __syncthreads();   // sP complete

        // GEMM2: mu/lv += P @ Wchunk   [256 x 16]
        #pragma unroll
        for (int q = 0; q < 2; ++q) {
            int rt2 = warp * 2 + q;
            #pragma unroll
            for (int k = 0; k < 4; ++k) {
                wmma::fragment<wmma::matrix_a, 16, 16, 16, half, wmma::row_major> fa;
                wmma::fragment<wmma::matrix_b, 16, 16, 16, half, wmma::row_major> fb;
                wmma::load_matrix_sync(fa, sP + rt2 * 16 * LDP + k * 16, LDP);
                wmma::load_matrix_sync(fb, sWmu + k * 16 * 16, 16);
                wmma::mma_sync(accMu[q], fa, fb, accMu[q]);
                wmma::load_matrix_sync(fb, sWlv + k * 16 * 16, 16);
                wmma::mma_sync(accLv[q], fa, fb, accLv[q]);
            }
        }
    }
    __syncthreads();

    // dump mu/lv to smem (overlaying sA, which is dead now)
    #pragma unroll
    for (int q = 0; q < 2; ++q) {
        int rt2 = warp * 2 + q;
        wmma::store_matrix_sync(sMu + rt2 * 16 * LDMU, accMu[q], LDMU, wmma::mem_row_major);
        wmma::store_matrix_sync(sLv + rt2 * 16 * LDMU, accLv[q], LDMU, wmma::mem_row_major);
    }
    if (tid < 16) { sTmp[tid] = bmu[tid]; sTmp[16 + tid] = blv[tid]; }
    __syncthreads();

    // epilogue: one row per thread
    int gr = r0 + tid;
    const float4* a4 = (const float4*)(actions + (size_t)gr * A);
    const float4* p4 = (const float4*)(blp + (size_t)gr * A);
    float lsum = 0.f;
    #pragma unroll
    for (int q = 0; q < 4; ++q) {
        float4 av = a4[q];
        float4 bv = p4[q];
        float aarr[4] = {av.x, av.y, av.z, av.w};
        float barr[4] = {bv.x, bv.y, bv.z, bv.w};
        #pragma unroll
        for (int j = 0; j < 4; ++j) {
            int col = q * 4 + j;
            float mu = sMu[tid * LDMU + col] + sTmp[col];
            float lv = sLv[tid * LDMU + col] + sTmp[16 + col];
            float d  = aarr[j] - mu;
            float logp = -0.5f * d * d * __expf(-lv) - 0.5f * lv - LOG_SQRT_2PI;
            lsum += logp - barr[j];
        }
    }
    float ratio = __expf(lsum);
    float ahat  = (g_adv[gr] - g_mean) * g_inv;
    float rc    = fminf(fmaxf(ratio, 1.f - EPSC), 1.f + EPSC);
    float term  = fminf(ratio * ahat, rc * ahat);

    float bsum = block_reduce_256(term, red8);
    if (tid == 0) atomicAdd(&g_actor, bsum);
}

// ---------------- K6: final scalar ----------------
__global__ void k_final(float* out) {
    out[0] = g_critic - g_actor / (float)T;
}

// ---------------- launch ----------------
extern "C" void kernel_launch(void* const* d_in, const int* in_sizes, int n_in,
                              void* d_out, int out_size) {
    const float* states  = (const float*)d_in[0];
    const float* actions = (const float*)d_in[1];
    const float* rewards = (const float*)d_in[2];
    const float* values  = (const float*)d_in[3];
    const float* blp     = (const float*)d_in[4];
    const float* W1      = (const float*)d_in[5];
    const float* b1      = (const float*)d_in[6];
    const float* Wmu     = (const float*)d_in[7];
    const float* bmu     = (const float*)d_in[8];
    const float* Wlv     = (const float*)d_in[9];
    const float* blv     = (const float*)d_in[10];
    const int*   masks   = (const int*)d_in[11];

    cudaFuncSetAttribute(k_main, cudaFuncAttributeMaxDynamicSharedMemorySize, SM_TOTAL);

    k_zero<<<1, 1>>>();
    k_scan1<<<256, 256>>>(rewards, masks);
    k_scan2<<<1, 256>>>();
    k_scan3<<<256, 256>>>(rewards, masks, values);
    k_stats<<<1, 1>>>();
    k_main<<<T / RT, 256, SM_TOTAL>>>(states, actions, blp, W1, b1, Wmu, bmu, Wlv, blv);
    k_final<<<1, 1>>>((float*)d_out);
}

// round 8
// speedup vs baseline: 1.3482x; 1.3482x over previous
#include <cuda_runtime.h>
#include <cuda_fp16.h>
#include <mma.h>

using namespace nvcuda;
typedef unsigned int uint;

static constexpr int   T = 262144;
static constexpr int   S = 128;
static constexpr int   H = 1024;
static constexpr int   A = 16;
static constexpr float GAMMA = 0.99f;
static constexpr float EPSC  = 0.2f;
static constexpr float LOG_SQRT_2PI = 0.91893853320467274178f;

// ---------------- device scratch (no allocation allowed) ----------------
__device__ float g_adv[T];
__device__ float g_blockA[256];
__device__ float g_blockB[256];
__device__ float g_blockInc[256];
__device__ float g_s1, g_s2, g_actor;
__device__ float g_mean, g_inv, g_critic;
__device__ __half g_W1h[S * H];     // [k][h]  fp16 copy of W1 (same layout)
__device__ __half g_Wmh[H * A];     // [h][a]
__device__ __half g_Wlh[H * A];     // [h][a]

// ---------------- helpers ----------------
__device__ __forceinline__ uint smem_u32(const void* p) {
    uint a;
    asm("{ .reg .u64 t; cvta.to.shared.u64 t, %1; cvt.u32.u64 %0, t; }" : "=r"(a) : "l"(p));
    return a;
}

#define CP_ASYNC16(dst, src) \
    asm volatile("cp.async.cg.shared.global [%0], [%1], 16;" :: "r"(dst), "l"(src))
#define CP_COMMIT() asm volatile("cp.async.commit_group;" ::: "memory")
#define CP_WAIT1()  asm volatile("cp.async.wait_group 1;" ::: "memory")
#define CP_WAIT0()  asm volatile("cp.async.wait_group 0;" ::: "memory")

__device__ __forceinline__ float tanh_fast(float x) {
    float y; asm("tanh.approx.f32 %0, %1;" : "=f"(y) : "f"(x)); return y;
}

__device__ __forceinline__ float block_reduce_256(float v, float* red8) {
    #pragma unroll
    for (int o = 16; o > 0; o >>= 1) v += __shfl_down_sync(0xffffffffu, v, o);
    if ((threadIdx.x & 31) == 0) red8[threadIdx.x >> 5] = v;
    __syncthreads();
    if (threadIdx.x < 8) {
        v = red8[threadIdx.x];
        #pragma unroll
        for (int o = 4; o > 0; o >>= 1) v += __shfl_down_sync(0xffu, v, o);
    }
    return v;
}

// ---------------- K0: zero ----------------
__global__ void k_zero() { g_s1 = 0.f; g_s2 = 0.f; g_actor = 0.f; }

// ---------------- Kp: pre-convert weights to fp16 (same layouts) ----------------
__global__ void k_prep(const float* __restrict__ W1, const float* __restrict__ Wmu,
                       const float* __restrict__ Wlv) {
    int idx = blockIdx.x * 256 + threadIdx.x;     // 0 .. 131071
    g_W1h[idx] = __float2half_rn(W1[idx]);
    if (idx < H * A) {
        g_Wmh[idx] = __float2half_rn(Wmu[idx]);
        g_Wlh[idx] = __float2half_rn(Wlv[idx]);
    }
}

// ---------------- K1..K4: masked discounted-return scan ----------------
__global__ void k_scan1(const float* __restrict__ rewards, const int* __restrict__ masks) {
    int blk = blockIdx.x, tid = threadIdx.x;
    int base = blk * 1024 + tid * 4;
    float4 r = *(const float4*)(rewards + base);
    int4   m = *(const int4*)(masks + base);
    float a = 1.f, b = 0.f, c;
    c = GAMMA * (float)m.w; b = r.w + c * b; a *= c;
    c = GAMMA * (float)m.z; b = r.z + c * b; a *= c;
    c = GAMMA * (float)m.y; b = r.y + c * b; a *= c;
    c = GAMMA * (float)m.x; b = r.x + c * b; a *= c;
    __shared__ float sa[256], sb[256];
    sa[tid] = a; sb[tid] = b;
    __syncthreads();
    if (tid == 0) {
        float Ab = 1.f, Bb = 0.f;
        for (int t = 255; t >= 0; --t) { Bb = sb[t] + sa[t] * Bb; Ab = sa[t] * Ab; }
        g_blockA[blk] = Ab; g_blockB[blk] = Bb;
    }
}

__global__ void k_scan2() {
    __shared__ float sa[256], sb[256], sinc[256];
    int tid = threadIdx.x;
    sa[tid] = g_blockA[tid]; sb[tid] = g_blockB[tid];
    __syncthreads();
    if (tid == 0) {
        float x = 0.f;
        for (int b = 255; b >= 0; --b) { sinc[b] = x; x = sb[b] + sa[b] * x; }
    }
    __syncthreads();
    g_blockInc[tid] = sinc[tid];
}

__global__ void k_scan3(const float* __restrict__ rewards, const int* __restrict__ masks,
                        const float* __restrict__ values) {
    int blk = blockIdx.x, tid = threadIdx.x;
    int base = blk * 1024 + tid * 4;
    float4 r = *(const float4*)(rewards + base);
    int4   m = *(const int4*)(masks + base);
    float c0 = GAMMA * (float)m.x, c1 = GAMMA * (float)m.y;
    float c2 = GAMMA * (float)m.z, c3 = GAMMA * (float)m.w;
    float a = 1.f, b = 0.f;
    b = r.w + c3 * b; a *= c3;
    b = r.z + c2 * b; a *= c2;
    b = r.y + c1 * b; a *= c1;
    b = r.x + c0 * b; a *= c0;
    __shared__ float sa[256], sb[256], sinc[256];
    __shared__ float red8[8];
    sa[tid] = a; sb[tid] = b;
    __syncthreads();
    if (tid == 0) {
        float x = g_blockInc[blk];
        for (int t = 255; t >= 0; --t) { sinc[t] = x; x = sb[t] + sa[t] * x; }
    }
    __syncthreads();
    float x = sinc[tid];
    float ret3 = r.w + c3 * x;
    float ret2 = r.z + c2 * ret3;
    float ret1 = r.y + c1 * ret2;
    float ret0 = r.x + c0 * ret1;
    float4 v = *(const float4*)(values + base);
    float4 adv = make_float4(ret0 - v.x, ret1 - v.y, ret2 - v.z, ret3 - v.w);
    *(float4*)(g_adv + base) = adv;
    float s1 = adv.x + adv.y + adv.z + adv.w;
    float s2 = adv.x * adv.x + adv.y * adv.y + adv.z * adv.z + adv.w * adv.w;
    float t1 = block_reduce_256(s1, red8);
    __syncthreads();
    float t2 = block_reduce_256(s2, red8);
    if (tid == 0) { atomicAdd(&g_s1, t1); atomicAdd(&g_s2, t2); }
}

__global__ void k_stats() {
    float s1 = g_s1, s2 = g_s2;
    float mean = s1 / (float)T;
    float var  = (s2 - s1 * mean) / (float)(T - 1);
    g_mean = mean;
    g_inv  = 1.f / (sqrtf(var) + 1e-7f);
    g_critic = s2 / (float)T;
}

// ---------------- K5: fused policy-net + PPO actor loss (WMMA, 2 CTA/SM) --------
static constexpr int RT  = 128;      // rows per CTA
static constexpr int NCH = 16;       // H chunks of 64
static constexpr int LDA = 136;      // half elems
static constexpr int LDW = 72;
static constexpr int LDP = 72;
static constexpr int LDMU = 20;      // float elems

static constexpr int SM_A    = 0;                              // 128*136*2 = 34816
static constexpr int SM_W1   = 34816;                          // 2 * 128*72*2 = 36864
static constexpr int W1_STRIDE = 128 * LDW * 2;                // 18432
static constexpr int SM_P    = 71680;                          // 128*72*2 = 18432
static constexpr int SM_TMP  = 90112;                          // 8*256*4 = 8192
static constexpr int SM_WM   = 98304;                          // 64*16*2 = 2048
static constexpr int SM_WL   = 100352;                         // 2048
static constexpr int SM_B1   = 102400;                         // 64*4
static constexpr int SM_BIAS = 102656;                         // 32*4
static constexpr int SM_RED  = 102784;                         // 8*4
static constexpr int SM_TOTAL = 102816;

__device__ __forceinline__ void load_w1_chunk_async(uint sb, int ch, int buf, int tid) {
    const char* src0 = (const char*)g_W1h + ch * 128;   // halves: row*1024 + ch*64
    #pragma unroll
    for (int i = 0; i < 4; ++i) {
        int o = tid + 256 * i;                // 0..1023
        int row = o >> 3, seg = o & 7;
        const char* src = src0 + (size_t)row * 2048 + seg * 16;
        uint dst = sb + SM_W1 + buf * W1_STRIDE + row * (LDW * 2) + seg * 16;
        CP_ASYNC16(dst, src);
    }
}

__global__ __launch_bounds__(256, 2)
void k_main(const float* __restrict__ states, const float* __restrict__ actions,
            const float* __restrict__ blp, const float* __restrict__ b1,
            const float* __restrict__ bmu, const float* __restrict__ blv) {
    extern __shared__ char smem[];
    uint sb = smem_u32(smem);
    half*  sA   = (half*)(smem + SM_A);
    half*  sP   = (half*)(smem + SM_P);
    float* sTmp = (float*)(smem + SM_TMP);
    half*  sWm  = (half*)(smem + SM_WM);
    half*  sWl  = (half*)(smem + SM_WL);
    float* sB1f = (float*)(smem + SM_B1);
    float* sBias= (float*)(smem + SM_BIAS);
    float* sRed = (float*)(smem + SM_RED);
    float* sMu  = (float*)(smem + SM_A);      // overlays sA after chunk loop
    float* sLv  = sMu + RT * LDMU;

    int tid  = threadIdx.x;
    int warp = tid >> 5, lane = tid & 31;
    int r0   = blockIdx.x * RT;

    if (tid < 16) { sBias[tid] = bmu[tid]; sBias[16 + tid] = blv[tid]; }

    // --- A tile: states [128 x 128] fp32 -> fp16 ---
    const float4* st4 = (const float4*)states + (size_t)r0 * 32;
    #pragma unroll
    for (int it = 0; it < 16; ++it) {
        int idx = tid + 256 * it;             // 4096 float4
        int row = idx >> 5, c4 = idx & 31;
        float4 v = st4[row * 32 + c4];
        half2* dst = (half2*)(sA + row * LDA + c4 * 4);
        dst[0] = __floats2half2_rn(v.x, v.y);
        dst[1] = __floats2half2_rn(v.z, v.w);
    }

    // --- prefetch W1 chunk 0 ---
    load_w1_chunk_async(sb, 0, 0, tid);
    CP_COMMIT();

    wmma::fragment<wmma::accumulator, 16, 16, 16, float> accMu, accLv;
    wmma::fill_fragment(accMu, 0.f);
    wmma::fill_fragment(accLv, 0.f);

    for (int ch = 0; ch < NCH; ++ch) {
        int buf = ch & 1;
        __syncthreads();    // prev GEMM2 done reading sP/sWm/sWl; sA writes visible (ch==0)

        // tiny sync loads: Wmu/Wlv chunk ch [64 x 16] + b1 chunk
        {
            int head = tid >> 7, o = tid & 127;       // 128 threads per head
            int row = o >> 1, seg = o & 1;
            const char* src = (const char*)(head ? g_Wlh : g_Wmh) + (size_t)(ch * 64 + row) * 32 + seg * 16;
            char* dst = (char*)(head ? sWl : sWm) + row * 32 + seg * 16;
            *(uint4*)dst = *(const uint4*)src;
        }
        if (tid < 64) sB1f[tid] = b1[ch * 64 + tid];

        // prefetch next W1 chunk, then make current chunk resident
        if (ch + 1 < NCH) {
            load_w1_chunk_async(sb, ch + 1, buf ^ 1, tid);
            CP_COMMIT();
            CP_WAIT1();
        } else {
            CP_WAIT0();
        }
        __syncthreads();    // W1 chunk ch + sWm/sWl/sB1 visible to all

        const half* sW1 = (half*)(smem + SM_W1 + buf * W1_STRIDE);

        // --- GEMM1: 16x64 strip per warp; acc in registers ---
        wmma::fragment<wmma::accumulator, 16, 16, 16, float> acc[4];
        #pragma unroll
        for (int tc = 0; tc < 4; ++tc) wmma::fill_fragment(acc[tc], 0.f);
        #pragma unroll
        for (int k = 0; k < 8; ++k) {
            wmma::fragment<wmma::matrix_a, 16, 16, 16, half, wmma::row_major> fa;
            wmma::load_matrix_sync(fa, sA + warp * 16 * LDA + k * 16, LDA);
            #pragma unroll
            for (int tc = 0; tc < 4; ++tc) {
                wmma::fragment<wmma::matrix_b, 16, 16, 16, half, wmma::row_major> fb;
                wmma::load_matrix_sync(fb, sW1 + k * 16 * LDW + tc * 16, LDW);
                wmma::mma_sync(acc[tc], fa, fb, acc[tc]);
            }
        }

        // --- epilogue: +b1, tanh -> fp16 sP (per-warp smem roundtrip) ---
        #pragma unroll
        for (int tc = 0; tc < 4; ++tc) {
            wmma::store_matrix_sync(sTmp + warp * 256, acc[tc], 16, wmma::mem_row_major);
            __syncwarp();
            #pragma unroll
            for (int i = 0; i < 8; ++i) {
                int pos = lane + 32 * i;
                int rr = pos >> 4, cc = pos & 15;
                float v = sTmp[warp * 256 + pos] + sB1f[tc * 16 + cc];
                sP[(warp * 16 + rr) * LDP + tc * 16 + cc] = __float2half_rn(tanh_fast(v));
            }
            __syncwarp();
        }
        __syncthreads();    // sP complete

        // --- GEMM2: mu/lv += P @ W{mu,lv}chunk ; one 16x16 tile per warp ---
        #pragma unroll
        for (int k = 0; k < 4; ++k) {
            wmma::fragment<wmma::matrix_a, 16, 16, 16, half, wmma::row_major> fa;
            wmma::fragment<wmma::matrix_b, 16, 16, 16, half, wmma::row_major> fb;
            wmma::load_matrix_sync(fa, sP + warp * 16 * LDP + k * 16, LDP);
            wmma::load_matrix_sync(fb, sWm + k * 16 * 16, 16);
            wmma::mma_sync(accMu, fa, fb, accMu);
            wmma::load_matrix_sync(fb, sWl + k * 16 * 16, 16);
            wmma::mma_sync(accLv, fa, fb, accLv);
        }
    }
    __syncthreads();

    // dump mu/lv (overlaying dead sA)
    wmma::store_matrix_sync(sMu + warp * 16 * LDMU, accMu, LDMU, wmma::mem_row_major);
    wmma::store_matrix_sync(sLv + warp * 16 * LDMU, accLv, LDMU, wmma::mem_row_major);
    __syncthreads();

    // --- loss epilogue: threads 0..127 own one row each ---
    float term = 0.f;
    if (tid < RT) {
        int gr = r0 + tid;
        const float4* a4 = (const float4*)(actions + (size_t)gr * A);
        const float4* p4 = (const float4*)(blp + (size_t)gr * A);
        float lsum = 0.f;
        #pragma unroll
        for (int q = 0; q < 4; ++q) {
            float4 av = a4[q];
            float4 bv = p4[q];
            float aarr[4] = {av.x, av.y, av.z, av.w};
            float barr[4] = {bv.x, bv.y, bv.z, bv.w};
            #pragma unroll
            for (int j = 0; j < 4; ++j) {
                int col = q * 4 + j;
                float mu = sMu[tid * LDMU + col] + sBias[col];
                float lv = sLv[tid * LDMU + col] + sBias[16 + col];
                float d  = aarr[j] - mu;
                float logp = -0.5f * d * d * __expf(-lv) - 0.5f * lv - LOG_SQRT_2PI;
                lsum += logp - barr[j];
            }
        }
        float ratio = __expf(lsum);
        float ahat  = (g_adv[gr] - g_mean) * g_inv;
        float rc    = fminf(fmaxf(ratio, 1.f - EPSC), 1.f + EPSC);
        term = fminf(ratio * ahat, rc * ahat);
    }
    float bsum = block_reduce_256(term, sRed);
    if (tid == 0) atomicAdd(&g_actor, bsum);
}

// ---------------- K6: final scalar ----------------
__global__ void k_final(float* out) {
    out[0] = g_critic - g_actor / (float)T;
}

// ---------------- launch ----------------
extern "C" void kernel_launch(void* const* d_in, const int* in_sizes, int n_in,
                              void* d_out, int out_size) {
    const float* states  = (const float*)d_in[0];
    const float* actions = (const float*)d_in[1];
    const float* rewards = (const float*)d_in[2];
    const float* values  = (const float*)d_in[3];
    const float* blp     = (const float*)d_in[4];
    const float* W1      = (const float*)d_in[5];
    const float* b1      = (const float*)d_in[6];
    const float* Wmu     = (const float*)d_in[7];
    const float* bmu     = (const float*)d_in[8];
    const float* Wlv     = (const float*)d_in[9];
    const float* blv     = (const float*)d_in[10];
    const int*   masks   = (const int*)d_in[11];

    cudaFuncSetAttribute(k_main, cudaFuncAttributeMaxDynamicSharedMemorySize, SM_TOTAL);

    k_zero<<<1, 1>>>();
    k_prep<<<512, 256>>>(W1, Wmu, Wlv);
    k_scan1<<<256, 256>>>(rewards, masks);
    k_scan2<<<1, 256>>>();
    k_scan3<<<256, 256>>>(rewards, masks, values);
    k_stats<<<1, 1>>>();
    k_main<<<T / RT, 256, SM_TOTAL>>>(states, actions, blp, b1, bmu, blv);
    k_final<<<1, 1>>>((float*)d_out);
}

// round 9
// speedup vs baseline: 2.4831x; 1.8417x over previous
#include <cuda_runtime.h>
#include <cuda_fp16.h>

typedef unsigned int uint;

static constexpr int   T = 262144;
static constexpr int   S = 128;
static constexpr int   H = 1024;
static constexpr int   A = 16;
static constexpr float GAMMA = 0.99f;
static constexpr float EPSC  = 0.2f;
static constexpr float LOG_SQRT_2PI = 0.91893853320467274178f;

// ---------------- device scratch (no allocation allowed) ----------------
__device__ float g_adv[T];
__device__ float g_blockA[256];
__device__ float g_blockB[256];
__device__ float g_blockInc[256];
__device__ float g_s1, g_s2, g_actor;
__device__ float g_mean, g_inv, g_critic;
__device__ __half g_W1h[S * H];     // [k][h]  fp16 copy of W1
__device__ __half g_Wmh[H * A];     // [h][a]
__device__ __half g_Wlh[H * A];     // [h][a]

// ---------------- helpers ----------------
__device__ __forceinline__ uint smem_u32(const void* p) {
    uint a;
    asm("{ .reg .u64 t; cvta.to.shared.u64 t, %1; cvt.u32.u64 %0, t; }" : "=r"(a) : "l"(p));
    return a;
}

#define CP_ASYNC16(dst, src) \
    asm volatile("cp.async.cg.shared.global [%0], [%1], 16;" :: "r"(dst), "l"(src))
#define CP_COMMIT() asm volatile("cp.async.commit_group;" ::: "memory")
#define CP_WAIT1()  asm volatile("cp.async.wait_group 1;" ::: "memory")
#define CP_WAIT0()  asm volatile("cp.async.wait_group 0;" ::: "memory")

#define LDSM_X4(r0, r1, r2, r3, addr) \
    asm volatile("ldmatrix.sync.aligned.m8n8.x4.shared.b16 {%0,%1,%2,%3}, [%4];" \
        : "=r"(r0), "=r"(r1), "=r"(r2), "=r"(r3) : "r"(addr))
#define LDSM_X4T(r0, r1, r2, r3, addr) \
    asm volatile("ldmatrix.sync.aligned.m8n8.x4.trans.shared.b16 {%0,%1,%2,%3}, [%4];" \
        : "=r"(r0), "=r"(r1), "=r"(r2), "=r"(r3) : "r"(addr))

#define MMA16816(d, a, b0, b1) \
    asm volatile("mma.sync.aligned.m16n8k16.row.col.f32.f16.f16.f32 " \
        "{%0,%1,%2,%3}, {%4,%5,%6,%7}, {%8,%9}, {%0,%1,%2,%3};" \
        : "+f"((d)[0]), "+f"((d)[1]), "+f"((d)[2]), "+f"((d)[3]) \
        : "r"((a)[0]), "r"((a)[1]), "r"((a)[2]), "r"((a)[3]), "r"(b0), "r"(b1))

__device__ __forceinline__ float tanh_fast(float x) {
    float y; asm("tanh.approx.f32 %0, %1;" : "=f"(y) : "f"(x)); return y;
}

__device__ __forceinline__ uint pack2(float x, float y) {
    half2 h = __floats2half2_rn(x, y);
    return *(uint*)&h;
}

__device__ __forceinline__ float block_reduce_256(float v, float* red8) {
    #pragma unroll
    for (int o = 16; o > 0; o >>= 1) v += __shfl_down_sync(0xffffffffu, v, o);
    if ((threadIdx.x & 31) == 0) red8[threadIdx.x >> 5] = v;
    __syncthreads();
    if (threadIdx.x < 8) {
        v = red8[threadIdx.x];
        #pragma unroll
        for (int o = 4; o > 0; o >>= 1) v += __shfl_down_sync(0xffu, v, o);
    }
    return v;
}

// ---------------- K0: zero ----------------
__global__ void k_zero() { g_s1 = 0.f; g_s2 = 0.f; g_actor = 0.f; }

// ---------------- Kp: pre-convert weights to fp16 ----------------
__global__ void k_prep(const float* __restrict__ W1, const float* __restrict__ Wmu,
                       const float* __restrict__ Wlv) {
    int idx = blockIdx.x * 256 + threadIdx.x;     // 0 .. 131071
    g_W1h[idx] = __float2half_rn(W1[idx]);
    if (idx < H * A) {
        g_Wmh[idx] = __float2half_rn(Wmu[idx]);
        g_Wlh[idx] = __float2half_rn(Wlv[idx]);
    }
}

// ---------------- K1..K4: masked discounted-return scan ----------------
__global__ void k_scan1(const float* __restrict__ rewards, const int* __restrict__ masks) {
    int blk = blockIdx.x, tid = threadIdx.x;
    int base = blk * 1024 + tid * 4;
    float4 r = *(const float4*)(rewards + base);
    int4   m = *(const int4*)(masks + base);
    float a = 1.f, b = 0.f, c;
    c = GAMMA * (float)m.w; b = r.w + c * b; a *= c;
    c = GAMMA * (float)m.z; b = r.z + c * b; a *= c;
    c = GAMMA * (float)m.y; b = r.y + c * b; a *= c;
    c = GAMMA * (float)m.x; b = r.x + c * b; a *= c;
    __shared__ float sa[256], sb[256];
    sa[tid] = a; sb[tid] = b;
    __syncthreads();
    if (tid == 0) {
        float Ab = 1.f, Bb = 0.f;
        for (int t = 255; t >= 0; --t) { Bb = sb[t] + sa[t] * Bb; Ab = sa[t] * Ab; }
        g_blockA[blk] = Ab; g_blockB[blk] = Bb;
    }
}

__global__ void k_scan2() {
    __shared__ float sa[256], sb[256], sinc[256];
    int tid = threadIdx.x;
    sa[tid] = g_blockA[tid]; sb[tid] = g_blockB[tid];
    __syncthreads();
    if (tid == 0) {
        float x = 0.f;
        for (int b = 255; b >= 0; --b) { sinc[b] = x; x = sb[b] + sa[b] * x; }
    }
    __syncthreads();
    g_blockInc[tid] = sinc[tid];
}

__global__ void k_scan3(const float* __restrict__ rewards, const int* __restrict__ masks,
                        const float* __restrict__ values) {
    int blk = blockIdx.x, tid = threadIdx.x;
    int base = blk * 1024 + tid * 4;
    float4 r = *(const float4*)(rewards + base);
    int4   m = *(const int4*)(masks + base);
    float c0 = GAMMA * (float)m.x, c1 = GAMMA * (float)m.y;
    float c2 = GAMMA * (float)m.z, c3 = GAMMA * (float)m.w;
    float a = 1.f, b = 0.f;
    b = r.w + c3 * b; a *= c3;
    b = r.z + c2 * b; a *= c2;
    b = r.y + c1 * b; a *= c1;
    b = r.x + c0 * b; a *= c0;
    __shared__ float sa[256], sb[256], sinc[256];
    __shared__ float red8[8];
    sa[tid] = a; sb[tid] = b;
    __syncthreads();
    if (tid == 0) {
        float x = g_blockInc[blk];
        for (int t = 255; t >= 0; --t) { sinc[t] = x; x = sb[t] + sa[t] * x; }
    }
    __syncthreads();
    float x = sinc[tid];
    float ret3 = r.w + c3 * x;
    float ret2 = r.z + c2 * ret3;
    float ret1 = r.y + c1 * ret2;
    float ret0 = r.x + c0 * ret1;
    float4 v = *(const float4*)(values + base);
    float4 adv = make_float4(ret0 - v.x, ret1 - v.y, ret2 - v.z, ret3 - v.w);
    *(float4*)(g_adv + base) = adv;
    float s1 = adv.x + adv.y + adv.z + adv.w;
    float s2 = adv.x * adv.x + adv.y * adv.y + adv.z * adv.z + adv.w * adv.w;
    float t1 = block_reduce_256(s1, red8);
    __syncthreads();
    float t2 = block_reduce_256(s2, red8);
    if (tid == 0) { atomicAdd(&g_s1, t1); atomicAdd(&g_s2, t2); }
}

__global__ void k_stats() {
    float s1 = g_s1, s2 = g_s2;
    float mean = s1 / (float)T;
    float var  = (s2 - s1 * mean) / (float)(T - 1);
    g_mean = mean;
    g_inv  = 1.f / (sqrtf(var) + 1e-7f);
    g_critic = s2 / (float)T;
}

// ---------------- K5: register-resident mma.sync pipeline ----------------
static constexpr int RT  = 128;      // rows per CTA
static constexpr int NCH = 16;       // H chunks of 64
static constexpr int LDA = 136;      // staging stride (halves)
static constexpr int LDW = 72;       // W1 smem stride (halves)
static constexpr int LD2 = 24;       // W2 smem stride (halves)
static constexpr int LDMU = 20;      // mu/lv overlay stride (floats)

static constexpr int SM_W1    = 0;                      // 2 x 128*72*2 = 36864 (A-stage overlays this)
static constexpr int W1_STRIDE = 128 * LDW * 2;         // 18432
static constexpr int SM_W2    = 36864;                  // 2 bufs x 2 heads x 64*24*2 = 12288
static constexpr int W2_STRIDE = 2 * 64 * LD2 * 2;      // 6144
static constexpr int W2_HEAD  = 64 * LD2 * 2;           // 3072
static constexpr int SM_B1    = 49152;                  // 1024 floats = 4096
static constexpr int SM_BIAS  = 53248;                  // 32 floats
static constexpr int SM_RED   = 53376;                  // 8 floats
static constexpr int SM_TOTAL = 53504;
// mu/lv overlay on dead W1 region after the loop:
static constexpr int SM_MU    = 0;                      // 128*20*4 = 10240
static constexpr int SM_LV    = 10240;

__device__ __forceinline__ void load_w1_chunk_async(uint sb, int ch, int buf, int tid) {
    const char* src0 = (const char*)g_W1h + ch * 128;   // + row*2048 + seg*16
    #pragma unroll
    for (int i = 0; i < 4; ++i) {
        int o = tid + 256 * i;                 // 0..1023
        int row = o >> 3, seg = o & 7;
        const char* src = src0 + (size_t)row * 2048 + seg * 16;
        uint dst = sb + SM_W1 + buf * W1_STRIDE + row * (LDW * 2) + seg * 16;
        CP_ASYNC16(dst, src);
    }
}

__device__ __forceinline__ void load_w2_chunk_async(uint sb, int ch, int buf, int tid) {
    // 2 heads x 64 rows x 2 segs = 256 transfers
    int head = tid >> 7, o = tid & 127;
    int row = o >> 1, seg = o & 1;
    const char* src = (const char*)(head ? g_Wlh : g_Wmh) + (size_t)(ch * 64 + row) * 32 + seg * 16;
    uint dst = sb + SM_W2 + buf * W2_STRIDE + head * W2_HEAD + row * (LD2 * 2) + seg * 16;
    CP_ASYNC16(dst, src);
}

__global__ __launch_bounds__(256, 2)
void k_main(const float* __restrict__ states, const float* __restrict__ actions,
            const float* __restrict__ blp, const float* __restrict__ b1,
            const float* __restrict__ bmu, const float* __restrict__ blv) {
    extern __shared__ char smem[];
    uint sb = smem_u32(smem);
    float* sB1f  = (float*)(smem + SM_B1);
    float* sBias = (float*)(smem + SM_BIAS);
    float* sRed  = (float*)(smem + SM_RED);

    int tid  = threadIdx.x;
    int warp = tid >> 5, lane = tid & 31;
    int r0   = blockIdx.x * RT;

    // ldmatrix lane geometry (shared by A, W1-B, W2-B loads)
    int lrow = lane & 15;           // matrix row within 16-row tile
    int lcol = (lane >> 4) * 8;     // 0 or 8 column offset

    if (tid < 16) { sBias[tid] = bmu[tid]; sBias[16 + tid] = blv[tid]; }
    ((float4*)sB1f)[tid] = ((const float4*)b1)[tid];   // all 1024 b1 floats

    // --- stage states tile [128 x 128] fp32->fp16 into W1 region (dead until ch0 loads) ---
    {
        half* sA = (half*)(smem + SM_W1);
        const float4* st4 = (const float4*)states + (size_t)r0 * 32;
        #pragma unroll
        for (int it = 0; it < 16; ++it) {
            int idx = tid + 256 * it;
            int row = idx >> 5, c4 = idx & 31;
            float4 v = st4[row * 32 + c4];
            half2* dst = (half2*)(sA + row * LDA + c4 * 4);
            dst[0] = __floats2half2_rn(v.x, v.y);
            dst[1] = __floats2half2_rn(v.z, v.w);
        }
    }
    __syncthreads();

    // --- A fragments: states held in registers for the whole kernel ---
    uint afr[8][4];
    {
        uint abase = sb + SM_W1 + ((warp * 16 + lrow) * LDA + lcol) * 2;
        #pragma unroll
        for (int ks = 0; ks < 8; ++ks)
            LDSM_X4(afr[ks][0], afr[ks][1], afr[ks][2], afr[ks][3], abase + ks * 32);
    }
    __syncthreads();   // all warps done reading the staging region

    // --- prefetch W1/W2 chunks 0,1 ---
    load_w1_chunk_async(sb, 0, 0, tid);
    load_w2_chunk_async(sb, 0, 0, tid);
    CP_COMMIT();
    load_w1_chunk_async(sb, 1, 1, tid);
    load_w2_chunk_async(sb, 1, 1, tid);
    CP_COMMIT();

    float muA0[4] = {0.f, 0.f, 0.f, 0.f}, muA1[4] = {0.f, 0.f, 0.f, 0.f};
    float lvA0[4] = {0.f, 0.f, 0.f, 0.f}, lvA1[4] = {0.f, 0.f, 0.f, 0.f};

    uint w1lane = sb + SM_W1 + (lrow * LDW + lcol) * 2;   // + buf*W1_STRIDE + ks*2304 + np*32
    uint w2lane = sb + SM_W2 + (lrow * LD2 + lcol) * 2;   // + buf*W2_STRIDE + head*W2_HEAD + np*768

    for (int ch = 0; ch < NCH; ++ch) {
        int buf = ch & 1;
        if (ch + 1 < NCH) CP_WAIT1(); else CP_WAIT0();
        __syncthreads();   // chunk ch buffers visible to all

        // --- GEMM1: acc[8 n-tiles] = states @ W1chunk ---
        float acc[8][4];
        #pragma unroll
        for (int nt = 0; nt < 8; ++nt) {
            acc[nt][0] = 0.f; acc[nt][1] = 0.f; acc[nt][2] = 0.f; acc[nt][3] = 0.f;
        }
        uint w1b = w1lane + buf * W1_STRIDE;
        #pragma unroll
        for (int ks = 0; ks < 8; ++ks) {
            #pragma unroll
            for (int np = 0; np < 4; ++np) {
                uint b0, b1r, b2, b3;
                LDSM_X4T(b0, b1r, b2, b3, w1b + ks * (16 * LDW * 2) + np * 32);
                MMA16816(acc[2 * np],     afr[ks], b0, b1r);
                MMA16816(acc[2 * np + 1], afr[ks], b2, b3);
            }
        }

        // --- epilogue in registers: +b1, tanh, pack -> A fragments for GEMM2 ---
        const float* b1c = sB1f + ch * 64 + (lane & 3) * 2;
        uint w2b = w2lane + buf * W2_STRIDE;
        #pragma unroll
        for (int np = 0; np < 4; ++np) {
            float2 be = *(const float2*)(b1c + np * 16);
            float2 bo = *(const float2*)(b1c + np * 16 + 8);
            float* e = acc[2 * np];
            float* o = acc[2 * np + 1];
            uint a2[4];
            a2[0] = pack2(tanh_fast(e[0] + be.x), tanh_fast(e[1] + be.y));
            a2[1] = pack2(tanh_fast(e[2] + be.x), tanh_fast(e[3] + be.y));
            a2[2] = pack2(tanh_fast(o[0] + bo.x), tanh_fast(o[1] + bo.y));
            a2[3] = pack2(tanh_fast(o[2] + bo.x), tanh_fast(o[3] + bo.y));

            uint m0, m1, m2, m3;
            LDSM_X4T(m0, m1, m2, m3, w2b + np * (16 * LD2 * 2));
            MMA16816(muA0, a2, m0, m1);
            MMA16816(muA1, a2, m2, m3);
            uint l0, l1, l2, l3;
            LDSM_X4T(l0, l1, l2, l3, w2b + W2_HEAD + np * (16 * LD2 * 2));
            MMA16816(lvA0, a2, l0, l1);
            MMA16816(lvA1, a2, l2, l3);
        }

        __syncthreads();   // all warps done reading buf(ch) before refill
        if (ch + 2 < NCH) {
            load_w1_chunk_async(sb, ch + 2, buf, tid);
            load_w2_chunk_async(sb, ch + 2, buf, tid);
            CP_COMMIT();
        }
    }

    // --- dump mu/lv to overlay (W1 region dead) ---
    __syncthreads();
    {
        float* sMu = (float*)(smem + SM_MU);
        float* sLv = (float*)(smem + SM_LV);
        int rr = warp * 16 + (lane >> 2);
        int cc = (lane & 3) * 2;
        *(float2*)&sMu[rr * LDMU + cc]           = make_float2(muA0[0], muA0[1]);
        *(float2*)&sMu[(rr + 8) * LDMU + cc]     = make_float2(muA0[2], muA0[3]);
        *(float2*)&sMu[rr * LDMU + cc + 8]       = make_float2(muA1[0], muA1[1]);
        *(float2*)&sMu[(rr + 8) * LDMU + cc + 8] = make_float2(muA1[2], muA1[3]);
        *(float2*)&sLv[rr * LDMU + cc]           = make_float2(lvA0[0], lvA0[1]);
        *(float2*)&sLv[(rr + 8) * LDMU + cc]     = make_float2(lvA0[2], lvA0[3]);
        *(float2*)&sLv[rr * LDMU + cc + 8]       = make_float2(lvA1[0], lvA1[1]);
        *(float2*)&sLv[(rr + 8) * LDMU + cc + 8] = make_float2(lvA1[2], lvA1[3]);
    }
    __syncthreads();

    // --- loss epilogue: threads 0..127 own one row each ---
    float term = 0.f;
    if (tid < RT) {
        const float* sMu = (const float*)(smem + SM_MU);
        const float* sLv = (const float*)(smem + SM_LV);
        int gr = r0 + tid;
        const float4* a4 = (const float4*)(actions + (size_t)gr * A);
        const float4* p4 = (const float4*)(blp + (size_t)gr * A);
        float lsum = 0.f;
        #pragma unroll
        for (int q = 0; q < 4; ++q) {
            float4 av = a4[q];
            float4 bv = p4[q];
            float aarr[4] = {av.x, av.y, av.z, av.w};
            float barr[4] = {bv.x, bv.y, bv.z, bv.w};
            #pragma unroll
            for (int j = 0; j < 4; ++j) {
                int col = q * 4 + j;
                float mu = sMu[tid * LDMU + col] + sBias[col];
                float lv = sLv[tid * LDMU + col] + sBias[16 + col];
                float d  = aarr[j] - mu;
                float logp = -0.5f * d * d * __expf(-lv) - 0.5f * lv - LOG_SQRT_2PI;
                lsum += logp - barr[j];
            }
        }
        float ratio = __expf(lsum);
        float ahat  = (g_adv[gr] - g_mean) * g_inv;
        float rc    = fminf(fmaxf(ratio, 1.f - EPSC), 1.f + EPSC);
        term = fminf(ratio * ahat, rc * ahat);
    }
    float bsum = block_reduce_256(term, sRed);
    if (tid == 0) atomicAdd(&g_actor, bsum);
}

// ---------------- K6: final scalar ----------------
__global__ void k_final(float* out) {
    out[0] = g_critic - g_actor / (float)T;
}

// ---------------- launch ----------------
extern "C" void kernel_launch(void* const* d_in, const int* in_sizes, int n_in,
                              void* d_out, int out_size) {
    const float* states  = (const float*)d_in[0];
    const float* actions = (const float*)d_in[1];
    const float* rewards = (const float*)d_in[2];
    const float* values  = (const float*)d_in[3];
    const float* blp     = (const float*)d_in[4];
    const float* W1      = (const float*)d_in[5];
    const float* b1      = (const float*)d_in[6];
    const float* Wmu     = (const float*)d_in[7];
    const float* bmu     = (const float*)d_in[8];
    const float* Wlv     = (const float*)d_in[9];
    const float* blv     = (const float*)d_in[10];
    const int*   masks   = (const int*)d_in[11];

    cudaFuncSetAttribute(k_main, cudaFuncAttributeMaxDynamicSharedMemorySize, SM_TOTAL);

    k_zero<<<1, 1>>>();
    k_prep<<<512, 256>>>(W1, Wmu, Wlv);
    k_scan1<<<256, 256>>>(rewards, masks);
    k_scan2<<<1, 256>>>();
    k_scan3<<<256, 256>>>(rewards, masks, values);
    k_stats<<<1, 1>>>();
    k_main<<<T / RT, 256, SM_TOTAL>>>(states, actions, blp, b1, bmu, blv);
    k_final<<<1, 1>>>((float*)d_out);
}

// round 10
// speedup vs baseline: 2.8900x; 1.1639x over previous
#include <cuda_runtime.h>
#include <cuda_fp16.h>

typedef unsigned int uint;

static constexpr int   T = 262144;
static constexpr int   S = 128;
static constexpr int   H = 1024;
static constexpr int   A = 16;
static constexpr float GAMMA = 0.99f;
static constexpr float EPSC  = 0.2f;
static constexpr float LOG_SQRT_2PI = 0.91893853320467274178f;

// ---------------- device scratch (no allocation allowed) ----------------
__device__ float g_adv[T];
__device__ float g_blockA[256];
__device__ float g_blockB[256];
__device__ float g_s1, g_s2, g_actor;
__device__ float g_mean, g_inv, g_critic;
__device__ uint  g_cnt_scan, g_cnt_main;
__device__ __half g_W1h[S * H];     // [k][h]  fp16 copy of W1
__device__ __half g_Wmh[H * A];     // [h][a]
__device__ __half g_Wlh[H * A];     // [h][a]

// ---------------- helpers ----------------
__device__ __forceinline__ uint smem_u32(const void* p) {
    uint a;
    asm("{ .reg .u64 t; cvta.to.shared.u64 t, %1; cvt.u32.u64 %0, t; }" : "=r"(a) : "l"(p));
    return a;
}

#define CP_ASYNC16(dst, src) \
    asm volatile("cp.async.cg.shared.global [%0], [%1], 16;" :: "r"(dst), "l"(src))
#define CP_COMMIT() asm volatile("cp.async.commit_group;" ::: "memory")
#define CP_WAIT1()  asm volatile("cp.async.wait_group 1;" ::: "memory")
#define CP_WAIT0()  asm volatile("cp.async.wait_group 0;" ::: "memory")

#define LDSM_X4(r0, r1, r2, r3, addr) \
    asm volatile("ldmatrix.sync.aligned.m8n8.x4.shared.b16 {%0,%1,%2,%3}, [%4];" \
        : "=r"(r0), "=r"(r1), "=r"(r2), "=r"(r3) : "r"(addr))
#define LDSM_X4T(r0, r1, r2, r3, addr) \
    asm volatile("ldmatrix.sync.aligned.m8n8.x4.trans.shared.b16 {%0,%1,%2,%3}, [%4];" \
        : "=r"(r0), "=r"(r1), "=r"(r2), "=r"(r3) : "r"(addr))

#define MMA16816(d, a, b0, b1) \
    asm volatile("mma.sync.aligned.m16n8k16.row.col.f32.f16.f16.f32 " \
        "{%0,%1,%2,%3}, {%4,%5,%6,%7}, {%8,%9}, {%0,%1,%2,%3};" \
        : "+f"((d)[0]), "+f"((d)[1]), "+f"((d)[2]), "+f"((d)[3]) \
        : "r"((a)[0]), "r"((a)[1]), "r"((a)[2]), "r"((a)[3]), "r"(b0), "r"(b1))

__device__ __forceinline__ float tanh_fast(float x) {
    float y; asm("tanh.approx.f32 %0, %1;" : "=f"(y) : "f"(x)); return y;
}

__device__ __forceinline__ uint pack2(float x, float y) {
    half2 h = __floats2half2_rn(x, y);
    return *(uint*)&h;
}

// ---------------- Kp: pre-convert weights + zero accumulators ----------------
__global__ void k_prep(const float* __restrict__ W1, const float* __restrict__ Wmu,
                       const float* __restrict__ Wlv) {
    int idx = blockIdx.x * 256 + threadIdx.x;     // 0 .. 131071
    g_W1h[idx] = __float2half_rn(W1[idx]);
    if (idx < H * A) {
        g_Wmh[idx] = __float2half_rn(Wmu[idx]);
        g_Wlh[idx] = __float2half_rn(Wlv[idx]);
    }
    if (idx == 0) {
        g_s1 = 0.f; g_s2 = 0.f; g_actor = 0.f;
        g_cnt_scan = 0u; g_cnt_main = 0u;
    }
}

// ---------------- K1: per-block affine composition (Kogge-Stone) ----------------
__global__ void k_scan1(const float* __restrict__ rewards, const int* __restrict__ masks) {
    int blk = blockIdx.x, tid = threadIdx.x;
    int base = blk * 1024 + tid * 4;
    float4 r = *(const float4*)(rewards + base);
    int4   m = *(const int4*)(masks + base);
    float a = 1.f, b = 0.f, c;
    c = GAMMA * (float)m.w; b = r.w + c * b; a *= c;
    c = GAMMA * (float)m.z; b = r.z + c * b; a *= c;
    c = GAMMA * (float)m.y; b = r.y + c * b; a *= c;
    c = GAMMA * (float)m.x; b = r.x + c * b; a *= c;
    __shared__ float sA[256], sB[256];
    sA[tid] = a; sB[tid] = b;
    __syncthreads();
    // suffix composition: P_t = T_t o T_{t+1} o ... o T_255
    #pragma unroll
    for (int o = 1; o < 256; o <<= 1) {
        float na = a, nb = b;
        if (tid + o < 256) { na = a * sA[tid + o]; nb = b + a * sB[tid + o]; }
        __syncthreads();
        sA[tid] = na; sB[tid] = nb; a = na; b = nb;
        __syncthreads();
    }
    if (tid == 0) { g_blockA[blk] = a; g_blockB[blk] = b; }
}

// ---------------- K2: apply scan + adv + sums + (last block) stats ----------------
__global__ void k_scan3(const float* __restrict__ rewards, const int* __restrict__ masks,
                        const float* __restrict__ values) {
    int blk = blockIdx.x, tid = threadIdx.x;
    int base = blk * 1024 + tid * 4;
    float4 r = *(const float4*)(rewards + base);
    int4   m = *(const int4*)(masks + base);
    float c0 = GAMMA * (float)m.x, c1 = GAMMA * (float)m.y;
    float c2 = GAMMA * (float)m.z, c3 = GAMMA * (float)m.w;
    float a = 1.f, b = 0.f;
    b = r.w + c3 * b; a *= c3;
    b = r.z + c2 * b; a *= c2;
    b = r.y + c1 * b; a *= c1;
    b = r.x + c0 * b; a *= c0;

    __shared__ float sA[256], sB[256];
    __shared__ float red8[8];

    // pass 1: suffix-scan the 256 block summaries; inc = P_{blk+1}(0)
    float ga = g_blockA[tid], gb = g_blockB[tid];
    sA[tid] = ga; sB[tid] = gb;
    __syncthreads();
    #pragma unroll
    for (int o = 1; o < 256; o <<= 1) {
        float na = ga, nb = gb;
        if (tid + o < 256) { na = ga * sA[tid + o]; nb = gb + ga * sB[tid + o]; }
        __syncthreads();
        sA[tid] = na; sB[tid] = nb; ga = na; gb = nb;
        __syncthreads();
    }
    float inc = (blk < 255) ? sB[blk + 1] : 0.f;
    __syncthreads();

    // pass 2: suffix-scan this block's own transforms; x_tid = Q_{tid+1}(inc)
    float qa = a, qb = b;
    sA[tid] = qa; sB[tid] = qb;
    __syncthreads();
    #pragma unroll
    for (int o = 1; o < 256; o <<= 1) {
        float na = qa, nb = qb;
        if (tid + o < 256) { na = qa * sA[tid + o]; nb = qb + qa * sB[tid + o]; }
        __syncthreads();
        sA[tid] = na; sB[tid] = nb; qa = na; qb = nb;
        __syncthreads();
    }
    float x = (tid < 255) ? (sA[tid + 1] * inc + sB[tid + 1]) : inc;

    float ret3 = r.w + c3 * x;
    float ret2 = r.z + c2 * ret3;
    float ret1 = r.y + c1 * ret2;
    float ret0 = r.x + c0 * ret1;
    float4 v = *(const float4*)(values + base);
    float4 adv = make_float4(ret0 - v.x, ret1 - v.y, ret2 - v.z, ret3 - v.w);
    *(float4*)(g_adv + base) = adv;
    float s1 = adv.x + adv.y + adv.z + adv.w;
    float s2 = adv.x * adv.x + adv.y * adv.y + adv.z * adv.z + adv.w * adv.w;

    // block reduce both sums
    #pragma unroll
    for (int o = 16; o > 0; o >>= 1) {
        s1 += __shfl_down_sync(0xffffffffu, s1, o);
        s2 += __shfl_down_sync(0xffffffffu, s2, o);
    }
    if ((tid & 31) == 0) { red8[tid >> 5] = s1; }
    __syncthreads();
    if ((tid & 31) == 0) { sA[tid >> 5] = s2; }   // reuse sA scratch
    __syncthreads();
    if (tid == 0) {
        float t1 = 0.f, t2 = 0.f;
        #pragma unroll
        for (int i = 0; i < 8; ++i) { t1 += red8[i]; t2 += sA[i]; }
        atomicAdd(&g_s1, t1);
        atomicAdd(&g_s2, t2);
        __threadfence();
        uint done = atomicAdd(&g_cnt_scan, 1u);
        if (done == 255u) {
            float S1 = atomicAdd(&g_s1, 0.f);
            float S2 = atomicAdd(&g_s2, 0.f);
            float mean = S1 / (float)T;
            float var  = (S2 - S1 * mean) / (float)(T - 1);
            g_mean = mean;
            g_inv  = 1.f / (sqrtf(var) + 1e-7f);
            g_critic = S2 / (float)T;
        }
    }
}

// ---------------- K5: mma.sync pipeline, M_warp=32 ----------------
static constexpr int RT  = 128;      // rows per CTA (4 warps x 32 rows)
static constexpr int NCH = 16;       // H chunks of 64
static constexpr int LDA = 136;      // staging stride (halves)
static constexpr int LDW = 72;       // W1 smem stride (halves)
static constexpr int LD2 = 24;       // W2 smem stride (halves)
static constexpr int LDMU = 20;      // mu/lv overlay stride (floats)

static constexpr int SM_W1    = 0;                      // 2 x 128*72*2 = 36864 (A-stage overlays)
static constexpr int W1_STRIDE = 128 * LDW * 2;         // 18432
static constexpr int SM_W2    = 36864;                  // 2 bufs x 2 heads x 64*24*2 = 12288
static constexpr int W2_STRIDE = 2 * 64 * LD2 * 2;      // 6144
static constexpr int W2_HEAD  = 64 * LD2 * 2;           // 3072
static constexpr int SM_B1    = 49152;                  // 1024 floats = 4096
static constexpr int SM_BIAS  = 53248;                  // 32 floats
static constexpr int SM_RED   = 53376;                  // 8 floats
static constexpr int SM_TOTAL = 53504;
static constexpr int SM_MU    = 0;                      // overlay on dead W1 region
static constexpr int SM_LV    = 10240;

__device__ __forceinline__ void load_w1_chunk_async(uint sb, int ch, int buf, int tid) {
    const char* src0 = (const char*)g_W1h + ch * 128;   // + row*2048 + seg*16
    #pragma unroll
    for (int i = 0; i < 8; ++i) {
        int o = tid + 128 * i;                 // 0..1023
        int row = o >> 3, seg = o & 7;
        const char* src = src0 + (size_t)row * 2048 + seg * 16;
        uint dst = sb + SM_W1 + buf * W1_STRIDE + row * (LDW * 2) + seg * 16;
        CP_ASYNC16(dst, src);
    }
}

__device__ __forceinline__ void load_w2_chunk_async(uint sb, int ch, int buf, int tid) {
    #pragma unroll
    for (int i = 0; i < 2; ++i) {
        int o = tid + 128 * i;                 // 0..255
        int head = o >> 7, w = o & 127;
        int row = w >> 1, seg = w & 1;
        const char* src = (const char*)(head ? g_Wlh : g_Wmh) + (size_t)(ch * 64 + row) * 32 + seg * 16;
        uint dst = sb + SM_W2 + buf * W2_STRIDE + head * W2_HEAD + row * (LD2 * 2) + seg * 16;
        CP_ASYNC16(dst, src);
    }
}

__global__ __launch_bounds__(128, 2)
void k_main(const float* __restrict__ states, const float* __restrict__ actions,
            const float* __restrict__ blp, const float* __restrict__ b1,
            const float* __restrict__ bmu, const float* __restrict__ blv,
            float* __restrict__ out) {
    extern __shared__ char smem[];
    uint sb = smem_u32(smem);
    float* sB1f  = (float*)(smem + SM_B1);
    float* sBias = (float*)(smem + SM_BIAS);
    float* sRed  = (float*)(smem + SM_RED);

    int tid  = threadIdx.x;
    int warp = tid >> 5, lane = tid & 31;
    int r0   = blockIdx.x * RT;

    int lrow = lane & 15;
    int lcol = (lane >> 4) * 8;

    if (tid < 16) { sBias[tid] = bmu[tid]; sBias[16 + tid] = blv[tid]; }
    #pragma unroll
    for (int i = 0; i < 2; ++i)
        ((float4*)sB1f)[tid + 128 * i] = ((const float4*)b1)[tid + 128 * i];

    // --- stage states tile [128 x 128] fp32->fp16 into W1 region ---
    {
        half* sAst = (half*)(smem + SM_W1);
        const float4* st4 = (const float4*)states + (size_t)r0 * 32;
        #pragma unroll
        for (int it = 0; it < 32; ++it) {
            int idx = tid + 128 * it;
            int row = idx >> 5, c4 = idx & 31;
            float4 v = st4[row * 32 + c4];
            half2* dst = (half2*)(sAst + row * LDA + c4 * 4);
            dst[0] = __floats2half2_rn(v.x, v.y);
            dst[1] = __floats2half2_rn(v.z, v.w);
        }
    }
    __syncthreads();

    // --- A fragments: 32 rows per warp, resident in registers ---
    uint afr[2][8][4];
    #pragma unroll
    for (int t = 0; t < 2; ++t) {
        uint abase = sb + SM_W1 + ((warp * 32 + t * 16 + lrow) * LDA + lcol) * 2;
        #pragma unroll
        for (int ks = 0; ks < 8; ++ks)
            LDSM_X4(afr[t][ks][0], afr[t][ks][1], afr[t][ks][2], afr[t][ks][3], abase + ks * 32);
    }
    __syncthreads();

    // --- prefetch chunks 0,1 ---
    load_w1_chunk_async(sb, 0, 0, tid);
    load_w2_chunk_async(sb, 0, 0, tid);
    CP_COMMIT();
    load_w1_chunk_async(sb, 1, 1, tid);
    load_w2_chunk_async(sb, 1, 1, tid);
    CP_COMMIT();

    float muL[2][4], muH[2][4], lvL[2][4], lvH[2][4];
    #pragma unroll
    for (int t = 0; t < 2; ++t)
        #pragma unroll
        for (int i = 0; i < 4; ++i) {
            muL[t][i] = 0.f; muH[t][i] = 0.f; lvL[t][i] = 0.f; lvH[t][i] = 0.f;
        }

    uint w1lane = sb + SM_W1 + (lrow * LDW + lcol) * 2;
    uint w2lane = sb + SM_W2 + (lrow * LD2 + lcol) * 2;

    for (int ch = 0; ch < NCH; ++ch) {
        int buf = ch & 1;
        if (ch + 1 < NCH) CP_WAIT1(); else CP_WAIT0();
        __syncthreads();

        // --- GEMM1: two row-tiles share every B fragment ---
        float acc0[8][4], acc1[8][4];
        #pragma unroll
        for (int nt = 0; nt < 8; ++nt)
            #pragma unroll
            for (int i = 0; i < 4; ++i) { acc0[nt][i] = 0.f; acc1[nt][i] = 0.f; }
        uint w1b = w1lane + buf * W1_STRIDE;
        #pragma unroll
        for (int ks = 0; ks < 8; ++ks) {
            #pragma unroll
            for (int np = 0; np < 4; ++np) {
                uint b0, b1r, b2, b3;
                LDSM_X4T(b0, b1r, b2, b3, w1b + ks * (16 * LDW * 2) + np * 32);
                MMA16816(acc0[2 * np],     afr[0][ks], b0, b1r);
                MMA16816(acc0[2 * np + 1], afr[0][ks], b2, b3);
                MMA16816(acc1[2 * np],     afr[1][ks], b0, b1r);
                MMA16816(acc1[2 * np + 1], afr[1][ks], b2, b3);
            }
        }

        // --- epilogue in registers + GEMM2 (W2 frags shared by both row-tiles) ---
        const float* b1c = sB1f + ch * 64 + (lane & 3) * 2;
        uint w2b = w2lane + buf * W2_STRIDE;
        #pragma unroll
        for (int np = 0; np < 4; ++np) {
            float2 be = *(const float2*)(b1c + np * 16);
            float2 bo = *(const float2*)(b1c + np * 16 + 8);
            uint a20[4], a21[4];
            {
                float* e = acc0[2 * np]; float* o = acc0[2 * np + 1];
                a20[0] = pack2(tanh_fast(e[0] + be.x), tanh_fast(e[1] + be.y));
                a20[1] = pack2(tanh_fast(e[2] + be.x), tanh_fast(e[3] + be.y));
                a20[2] = pack2(tanh_fast(o[0] + bo.x), tanh_fast(o[1] + bo.y));
                a20[3] = pack2(tanh_fast(o[2] + bo.x), tanh_fast(o[3] + bo.y));
            }
            {
                float* e = acc1[2 * np]; float* o = acc1[2 * np + 1];
                a21[0] = pack2(tanh_fast(e[0] + be.x), tanh_fast(e[1] + be.y));
                a21[1] = pack2(tanh_fast(e[2] + be.x), tanh_fast(e[3] + be.y));
                a21[2] = pack2(tanh_fast(o[0] + bo.x), tanh_fast(o[1] + bo.y));
                a21[3] = pack2(tanh_fast(o[2] + bo.x), tanh_fast(o[3] + bo.y));
            }
            uint m0, m1, m2, m3;
            LDSM_X4T(m0, m1, m2, m3, w2b + np * (16 * LD2 * 2));
            MMA16816(muL[0], a20, m0, m1);
            MMA16816(muH[0], a20, m2, m3);
            MMA16816(muL[1], a21, m0, m1);
            MMA16816(muH[1], a21, m2, m3);
            uint l0, l1, l2, l3;
            LDSM_X4T(l0, l1, l2, l3, w2b + W2_HEAD + np * (16 * LD2 * 2));
            MMA16816(lvL[0], a20, l0, l1);
            MMA16816(lvH[0], a20, l2, l3);
            MMA16816(lvL[1], a21, l0, l1);
            MMA16816(lvH[1], a21, l2, l3);
        }

        __syncthreads();
        if (ch + 2 < NCH) {
            load_w1_chunk_async(sb, ch + 2, buf, tid);
            load_w2_chunk_async(sb, ch + 2, buf, tid);
            CP_COMMIT();
        }
    }

    // --- dump mu/lv to overlay (W1 region dead) ---
    __syncthreads();
    {
        float* sMu = (float*)(smem + SM_MU);
        float* sLv = (float*)(smem + SM_LV);
        int cc = (lane & 3) * 2;
        #pragma unroll
        for (int t = 0; t < 2; ++t) {
            int rr = warp * 32 + t * 16 + (lane >> 2);
            *(float2*)&sMu[rr * LDMU + cc]           = make_float2(muL[t][0], muL[t][1]);
            *(float2*)&sMu[(rr + 8) * LDMU + cc]     = make_float2(muL[t][2], muL[t][3]);
            *(float2*)&sMu[rr * LDMU + cc + 8]       = make_float2(muH[t][0], muH[t][1]);
            *(float2*)&sMu[(rr + 8) * LDMU + cc + 8] = make_float2(muH[t][2], muH[t][3]);
            *(float2*)&sLv[rr * LDMU + cc]           = make_float2(lvL[t][0], lvL[t][1]);
            *(float2*)&sLv[(rr + 8) * LDMU + cc]     = make_float2(lvL[t][2], lvL[t][3]);
            *(float2*)&sLv[rr * LDMU + cc + 8]       = make_float2(lvH[t][0], lvH[t][1]);
            *(float2*)&sLv[(rr + 8) * LDMU + cc + 8] = make_float2(lvH[t][2], lvH[t][3]);
        }
    }
    __syncthreads();

    // --- loss epilogue: each thread owns one row ---
    const float* sMu = (const float*)(smem + SM_MU);
    const float* sLv = (const float*)(smem + SM_LV);
    int gr = r0 + tid;
    const float4* a4 = (const float4*)(actions + (size_t)gr * A);
    const float4* p4 = (const float4*)(blp + (size_t)gr * A);
    float lsum = 0.f;
    #pragma unroll
    for (int q = 0; q < 4; ++q) {
        float4 av = a4[q];
        float4 bv = p4[q];
        float aarr[4] = {av.x, av.y, av.z, av.w};
        float barr[4] = {bv.x, bv.y, bv.z, bv.w};
        #pragma unroll
        for (int j = 0; j < 4; ++j) {
            int col = q * 4 + j;
            float mu = sMu[tid * LDMU + col] + sBias[col];
            float lv = sLv[tid * LDMU + col] + sBias[16 + col];
            float d  = aarr[j] - mu;
            float logp = -0.5f * d * d * __expf(-lv) - 0.5f * lv - LOG_SQRT_2PI;
            lsum += logp - barr[j];
        }
    }
    float ratio = __expf(lsum);
    float ahat  = (g_adv[gr] - g_mean) * g_inv;
    float rc    = fminf(fmaxf(ratio, 1.f - EPSC), 1.f + EPSC);
    float term  = fminf(ratio * ahat, rc * ahat);

    #pragma unroll
    for (int o = 16; o > 0; o >>= 1) term += __shfl_down_sync(0xffffffffu, term, o);
    if ((tid & 31) == 0) sRed[warp] = term;
    __syncthreads();
    if (tid == 0) {
        float bsum = sRed[0] + sRed[1] + sRed[2] + sRed[3];
        atomicAdd(&g_actor, bsum);
        __threadfence();
        uint done = atomicAdd(&g_cnt_main, 1u);
        if (done == (uint)(gridDim.x - 1)) {
            float actor = atomicAdd(&g_actor, 0.f);
            out[0] = g_critic - actor / (float)T;
        }
    }
}

// ---------------- launch ----------------
extern "C" void kernel_launch(void* const* d_in, const int* in_sizes, int n_in,
                              void* d_out, int out_size) {
    const float* states  = (const float*)d_in[0];
    const float* actions = (const float*)d_in[1];
    const float* rewards = (const float*)d_in[2];
    const float* values  = (const float*)d_in[3];
    const float* blp     = (const float*)d_in[4];
    const float* W1      = (const float*)d_in[5];
    const float* b1      = (const float*)d_in[6];
    const float* Wmu     = (const float*)d_in[7];
    const float* bmu     = (const float*)d_in[8];
    const float* Wlv     = (const float*)d_in[9];
    const float* blv     = (const float*)d_in[10];
    const int*   masks   = (const int*)d_in[11];

    cudaFuncSetAttribute(k_main, cudaFuncAttributeMaxDynamicSharedMemorySize, SM_TOTAL);

    k_prep<<<512, 256>>>(W1, Wmu, Wlv);
    k_scan1<<<256, 256>>>(rewards, masks);
    k_scan3<<<256, 256>>>(rewards, masks, values);
    k_main<<<T / RT, 128, SM_TOTAL>>>(states, actions, blp, b1, bmu, blv, (float*)d_out);
}

// round 11
// speedup vs baseline: 2.9241x; 1.0118x over previous
#include <cuda_runtime.h>
#include <cuda_fp16.h>

typedef unsigned int uint;

static constexpr int   T = 262144;
static constexpr int   S = 128;
static constexpr int   H = 1024;
static constexpr int   A = 16;
static constexpr float GAMMA = 0.99f;
static constexpr float EPSC  = 0.2f;
static constexpr float LOG_SQRT_2PI = 0.91893853320467274178f;

// ---------------- device scratch (no allocation allowed) ----------------
__device__ float g_adv[T];
__device__ float g_blockA[256];
__device__ float g_blockB[256];
__device__ float g_s1, g_s2, g_actor;
__device__ float g_mean, g_inv, g_critic;
__device__ uint  g_cnt_scan, g_cnt_main;
__device__ __half g_W1h[S * H];     // [k][h]  fp16 copy of W1
__device__ __half g_Wmh[H * A];     // [h][a]
__device__ __half g_Wlh[H * A];     // [h][a]
__device__ uint   g_b1h[H / 2];     // b1 packed as half2 pairs

// ---------------- helpers ----------------
__device__ __forceinline__ uint smem_u32(const void* p) {
    uint a;
    asm("{ .reg .u64 t; cvta.to.shared.u64 t, %1; cvt.u32.u64 %0, t; }" : "=r"(a) : "l"(p));
    return a;
}

#define CP_ASYNC16(dst, src) \
    asm volatile("cp.async.cg.shared.global [%0], [%1], 16;" :: "r"(dst), "l"(src))
#define CP_COMMIT() asm volatile("cp.async.commit_group;" ::: "memory")
#define CP_WAIT1()  asm volatile("cp.async.wait_group 1;" ::: "memory")
#define CP_WAIT0()  asm volatile("cp.async.wait_group 0;" ::: "memory")

#define LDSM_X4(r0, r1, r2, r3, addr) \
    asm volatile("ldmatrix.sync.aligned.m8n8.x4.shared.b16 {%0,%1,%2,%3}, [%4];" \
        : "=r"(r0), "=r"(r1), "=r"(r2), "=r"(r3) : "r"(addr))
#define LDSM_X4T(r0, r1, r2, r3, addr) \
    asm volatile("ldmatrix.sync.aligned.m8n8.x4.trans.shared.b16 {%0,%1,%2,%3}, [%4];" \
        : "=r"(r0), "=r"(r1), "=r"(r2), "=r"(r3) : "r"(addr))

// fp32-accumulate mma (GEMM2)
#define MMA16816(d, a, b0, b1) \
    asm volatile("mma.sync.aligned.m16n8k16.row.col.f32.f16.f16.f32 " \
        "{%0,%1,%2,%3}, {%4,%5,%6,%7}, {%8,%9}, {%0,%1,%2,%3};" \
        : "+f"((d)[0]), "+f"((d)[1]), "+f"((d)[2]), "+f"((d)[3]) \
        : "r"((a)[0]), "r"((a)[1]), "r"((a)[2]), "r"((a)[3]), "r"(b0), "r"(b1))

// fp16-accumulate mma (GEMM1, 2x rate)
#define MMA16816H(d, a, b0, b1) \
    asm volatile("mma.sync.aligned.m16n8k16.row.col.f16.f16.f16.f16 " \
        "{%0,%1}, {%2,%3,%4,%5}, {%6,%7}, {%0,%1};" \
        : "+r"((d)[0]), "+r"((d)[1]) \
        : "r"((a)[0]), "r"((a)[1]), "r"((a)[2]), "r"((a)[3]), "r"(b0), "r"(b1))

__device__ __forceinline__ uint htanh2(uint x) {
    uint y; asm("tanh.approx.f16x2 %0, %1;" : "=r"(y) : "r"(x)); return y;
}
__device__ __forceinline__ uint hadd2u(uint x, uint y) {
    uint z; asm("add.f16x2 %0, %1, %2;" : "=r"(z) : "r"(x), "r"(y)); return z;
}

// ---------------- Kp: pre-convert weights + pack b1 + zero accumulators ------
__global__ void k_prep(const float* __restrict__ W1, const float* __restrict__ Wmu,
                       const float* __restrict__ Wlv, const float* __restrict__ b1) {
    int idx = blockIdx.x * 256 + threadIdx.x;     // 0 .. 131071
    g_W1h[idx] = __float2half_rn(W1[idx]);
    if (idx < H * A) {
        g_Wmh[idx] = __float2half_rn(Wmu[idx]);
        g_Wlh[idx] = __float2half_rn(Wlv[idx]);
    }
    if (idx < H / 2) {
        half2 p = __floats2half2_rn(b1[2 * idx], b1[2 * idx + 1]);
        g_b1h[idx] = *(uint*)&p;
    }
    if (idx == 0) {
        g_s1 = 0.f; g_s2 = 0.f; g_actor = 0.f;
        g_cnt_scan = 0u; g_cnt_main = 0u;
    }
}

// ---------------- K1: per-block affine composition (Kogge-Stone) ----------------
__global__ void k_scan1(const float* __restrict__ rewards, const int* __restrict__ masks) {
    int blk = blockIdx.x, tid = threadIdx.x;
    int base = blk * 1024 + tid * 4;
    float4 r = *(const float4*)(rewards + base);
    int4   m = *(const int4*)(masks + base);
    float a = 1.f, b = 0.f, c;
    c = GAMMA * (float)m.w; b = r.w + c * b; a *= c;
    c = GAMMA * (float)m.z; b = r.z + c * b; a *= c;
    c = GAMMA * (float)m.y; b = r.y + c * b; a *= c;
    c = GAMMA * (float)m.x; b = r.x + c * b; a *= c;
    __shared__ float sA[256], sB[256];
    sA[tid] = a; sB[tid] = b;
    __syncthreads();
    #pragma unroll
    for (int o = 1; o < 256; o <<= 1) {
        float na = a, nb = b;
        if (tid + o < 256) { na = a * sA[tid + o]; nb = b + a * sB[tid + o]; }
        __syncthreads();
        sA[tid] = na; sB[tid] = nb; a = na; b = nb;
        __syncthreads();
    }
    if (tid == 0) { g_blockA[blk] = a; g_blockB[blk] = b; }
}

// ---------------- K2: apply scan + adv + sums + (last block) stats ----------------
__global__ void k_scan3(const float* __restrict__ rewards, const int* __restrict__ masks,
                        const float* __restrict__ values) {
    int blk = blockIdx.x, tid = threadIdx.x;
    int base = blk * 1024 + tid * 4;
    float4 r = *(const float4*)(rewards + base);
    int4   m = *(const int4*)(masks + base);
    float c0 = GAMMA * (float)m.x, c1 = GAMMA * (float)m.y;
    float c2 = GAMMA * (float)m.z, c3 = GAMMA * (float)m.w;
    float a = 1.f, b = 0.f;
    b = r.w + c3 * b; a *= c3;
    b = r.z + c2 * b; a *= c2;
    b = r.y + c1 * b; a *= c1;
    b = r.x + c0 * b; a *= c0;

    __shared__ float sA[256], sB[256];
    __shared__ float red8[8];

    float ga = g_blockA[tid], gb = g_blockB[tid];
    sA[tid] = ga; sB[tid] = gb;
    __syncthreads();
    #pragma unroll
    for (int o = 1; o < 256; o <<= 1) {
        float na = ga, nb = gb;
        if (tid + o < 256) { na = ga * sA[tid + o]; nb = gb + ga * sB[tid + o]; }
        __syncthreads();
        sA[tid] = na; sB[tid] = nb; ga = na; gb = nb;
        __syncthreads();
    }
    float inc = (blk < 255) ? sB[blk + 1] : 0.f;
    __syncthreads();

    float qa = a, qb = b;
    sA[tid] = qa; sB[tid] = qb;
    __syncthreads();
    #pragma unroll
    for (int o = 1; o < 256; o <<= 1) {
        float na = qa, nb = qb;
        if (tid + o < 256) { na = qa * sA[tid + o]; nb = qb + qa * sB[tid + o]; }
        __syncthreads();
        sA[tid] = na; sB[tid] = nb; qa = na; qb = nb;
        __syncthreads();
    }
    float x = (tid < 255) ? (sA[tid + 1] * inc + sB[tid + 1]) : inc;

    float ret3 = r.w + c3 * x;
    float ret2 = r.z + c2 * ret3;
    float ret1 = r.y + c1 * ret2;
    float ret0 = r.x + c0 * ret1;
    float4 v = *(const float4*)(values + base);
    float4 adv = make_float4(ret0 - v.x, ret1 - v.y, ret2 - v.z, ret3 - v.w);
    *(float4*)(g_adv + base) = adv;
    float s1 = adv.x + adv.y + adv.z + adv.w;
    float s2 = adv.x * adv.x + adv.y * adv.y + adv.z * adv.z + adv.w * adv.w;

    #pragma unroll
    for (int o = 16; o > 0; o >>= 1) {
        s1 += __shfl_down_sync(0xffffffffu, s1, o);
        s2 += __shfl_down_sync(0xffffffffu, s2, o);
    }
    if ((tid & 31) == 0) { red8[tid >> 5] = s1; }
    __syncthreads();
    if ((tid & 31) == 0) { sA[tid >> 5] = s2; }
    __syncthreads();
    if (tid == 0) {
        float t1 = 0.f, t2 = 0.f;
        #pragma unroll
        for (int i = 0; i < 8; ++i) { t1 += red8[i]; t2 += sA[i]; }
        atomicAdd(&g_s1, t1);
        atomicAdd(&g_s2, t2);
        __threadfence();
        uint done = atomicAdd(&g_cnt_scan, 1u);
        if (done == 255u) {
            float S1 = atomicAdd(&g_s1, 0.f);
            float S2 = atomicAdd(&g_s2, 0.f);
            float mean = S1 / (float)T;
            float var  = (S2 - S1 * mean) / (float)(T - 1);
            g_mean = mean;
            g_inv  = 1.f / (sqrtf(var) + 1e-7f);
            g_critic = S2 / (float)T;
        }
    }
}

// ---------------- K5: mma.sync pipeline, M_warp=32, f16-acc GEMM1 ----------------
static constexpr int RT  = 128;      // rows per CTA (4 warps x 32 rows)
static constexpr int NCH = 16;       // H chunks of 64
static constexpr int LDA = 136;      // staging stride (halves)
static constexpr int LDW = 72;       // W1 smem stride (halves)
static constexpr int LD2 = 24;       // W2 smem stride (halves)
static constexpr int LDMU = 20;      // mu/lv overlay stride (floats)

static constexpr int SM_W1    = 0;                      // 2 x 128*72*2 = 36864 (A-stage overlays)
static constexpr int W1_STRIDE = 128 * LDW * 2;         // 18432
static constexpr int SM_W2    = 36864;                  // 2 bufs x 2 heads x 64*24*2 = 12288
static constexpr int W2_STRIDE = 2 * 64 * LD2 * 2;      // 6144
static constexpr int W2_HEAD  = 64 * LD2 * 2;           // 3072
static constexpr int SM_B1H   = 49152;                  // 512 uints = 2048
static constexpr int SM_BIAS  = 51200;                  // 32 floats
static constexpr int SM_RED   = 51328;                  // 8 floats
static constexpr int SM_TOTAL = 51456;
static constexpr int SM_MU    = 0;                      // overlay on dead W1 region
static constexpr int SM_LV    = 10240;

__device__ __forceinline__ void load_w1_chunk_async(uint sb, int ch, int buf, int tid) {
    const char* src0 = (const char*)g_W1h + ch * 128;   // + row*2048 + seg*16
    #pragma unroll
    for (int i = 0; i < 8; ++i) {
        int o = tid + 128 * i;                 // 0..1023
        int row = o >> 3, seg = o & 7;
        const char* src = src0 + (size_t)row * 2048 + seg * 16;
        uint dst = sb + SM_W1 + buf * W1_STRIDE + row * (LDW * 2) + seg * 16;
        CP_ASYNC16(dst, src);
    }
}

__device__ __forceinline__ void load_w2_chunk_async(uint sb, int ch, int buf, int tid) {
    #pragma unroll
    for (int i = 0; i < 2; ++i) {
        int o = tid + 128 * i;                 // 0..255
        int head = o >> 7, w = o & 127;
        int row = w >> 1, seg = w & 1;
        const char* src = (const char*)(head ? g_Wlh : g_Wmh) + (size_t)(ch * 64 + row) * 32 + seg * 16;
        uint dst = sb + SM_W2 + buf * W2_STRIDE + head * W2_HEAD + row * (LD2 * 2) + seg * 16;
        CP_ASYNC16(dst, src);
    }
}

__global__ __launch_bounds__(128, 2)
void k_main(const float* __restrict__ states, const float* __restrict__ actions,
            const float* __restrict__ blp,
            const float* __restrict__ bmu, const float* __restrict__ blv,
            float* __restrict__ out) {
    extern __shared__ char smem[];
    uint sb = smem_u32(smem);
    uint*  sB1h  = (uint*)(smem + SM_B1H);
    float* sBias = (float*)(smem + SM_BIAS);
    float* sRed  = (float*)(smem + SM_RED);

    int tid  = threadIdx.x;
    int warp = tid >> 5, lane = tid & 31;
    int r0   = blockIdx.x * RT;

    int lrow = lane & 15;
    int lcol = (lane >> 4) * 8;

    if (tid < 16) { sBias[tid] = bmu[tid]; sBias[16 + tid] = blv[tid]; }
    ((uint4*)sB1h)[tid] = ((const uint4*)g_b1h)[tid];   // 512 uints

    // --- stage states tile [128 x 128] fp32->fp16 into W1 region ---
    {
        half* sAst = (half*)(smem + SM_W1);
        const float4* st4 = (const float4*)states + (size_t)r0 * 32;
        #pragma unroll
        for (int it = 0; it < 32; ++it) {
            int idx = tid + 128 * it;
            int row = idx >> 5, c4 = idx & 31;
            float4 v = st4[row * 32 + c4];
            half2* dst = (half2*)(sAst + row * LDA + c4 * 4);
            dst[0] = __floats2half2_rn(v.x, v.y);
            dst[1] = __floats2half2_rn(v.z, v.w);
        }
    }
    __syncthreads();

    // --- A fragments: 32 rows per warp, resident in registers ---
    uint afr[2][8][4];
    #pragma unroll
    for (int t = 0; t < 2; ++t) {
        uint abase = sb + SM_W1 + ((warp * 32 + t * 16 + lrow) * LDA + lcol) * 2;
        #pragma unroll
        for (int ks = 0; ks < 8; ++ks)
            LDSM_X4(afr[t][ks][0], afr[t][ks][1], afr[t][ks][2], afr[t][ks][3], abase + ks * 32);
    }
    __syncthreads();

    // --- prefetch chunks 0,1 ---
    load_w1_chunk_async(sb, 0, 0, tid);
    load_w2_chunk_async(sb, 0, 0, tid);
    CP_COMMIT();
    load_w1_chunk_async(sb, 1, 1, tid);
    load_w2_chunk_async(sb, 1, 1, tid);
    CP_COMMIT();

    float muL[2][4], muH[2][4], lvL[2][4], lvH[2][4];
    #pragma unroll
    for (int t = 0; t < 2; ++t)
        #pragma unroll
        for (int i = 0; i < 4; ++i) {
            muL[t][i] = 0.f; muH[t][i] = 0.f; lvL[t][i] = 0.f; lvH[t][i] = 0.f;
        }

    uint w1lane = sb + SM_W1 + (lrow * LDW + lcol) * 2;
    uint w2lane = sb + SM_W2 + (lrow * LD2 + lcol) * 2;

    for (int ch = 0; ch < NCH; ++ch) {
        int buf = ch & 1;
        if (ch + 1 < NCH) CP_WAIT1(); else CP_WAIT0();
        __syncthreads();

        // --- GEMM1 (f16 acc, 2x rate): two row-tiles share every B fragment ---
        uint acc0[8][2], acc1[8][2];
        #pragma unroll
        for (int nt = 0; nt < 8; ++nt) {
            acc0[nt][0] = 0u; acc0[nt][1] = 0u;
            acc1[nt][0] = 0u; acc1[nt][1] = 0u;
        }
        uint w1b = w1lane + buf * W1_STRIDE;
        #pragma unroll
        for (int ks = 0; ks < 8; ++ks) {
            #pragma unroll
            for (int np = 0; np < 4; ++np) {
                uint b0, b1r, b2, b3;
                LDSM_X4T(b0, b1r, b2, b3, w1b + ks * (16 * LDW * 2) + np * 32);
                MMA16816H(acc0[2 * np],     afr[0][ks], b0, b1r);
                MMA16816H(acc0[2 * np + 1], afr[0][ks], b2, b3);
                MMA16816H(acc1[2 * np],     afr[1][ks], b0, b1r);
                MMA16816H(acc1[2 * np + 1], afr[1][ks], b2, b3);
            }
        }

        // --- epilogue: HADD2 bias + tanh.f16x2 -> A fragments; GEMM2 fp32 acc ---
        const uint* b1c = sB1h + ch * 32 + (lane & 3);
        uint w2b = w2lane + buf * W2_STRIDE;
        #pragma unroll
        for (int np = 0; np < 4; ++np) {
            uint be = b1c[np * 8];
            uint bo = b1c[np * 8 + 4];
            uint a20[4], a21[4];
            a20[0] = htanh2(hadd2u(acc0[2 * np][0],     be));
            a20[1] = htanh2(hadd2u(acc0[2 * np][1],     be));
            a20[2] = htanh2(hadd2u(acc0[2 * np + 1][0], bo));
            a20[3] = htanh2(hadd2u(acc0[2 * np + 1][1], bo));
            a21[0] = htanh2(hadd2u(acc1[2 * np][0],     be));
            a21[1] = htanh2(hadd2u(acc1[2 * np][1],     be));
            a21[2] = htanh2(hadd2u(acc1[2 * np + 1][0], bo));
            a21[3] = htanh2(hadd2u(acc1[2 * np + 1][1], bo));

            uint m0, m1, m2, m3;
            LDSM_X4T(m0, m1, m2, m3, w2b + np * (16 * LD2 * 2));
            MMA16816(muL[0], a20, m0, m1);
            MMA16816(muH[0], a20, m2, m3);
            MMA16816(muL[1], a21, m0, m1);
            MMA16816(muH[1], a21, m2, m3);
            uint l0, l1, l2, l3;
            LDSM_X4T(l0, l1, l2, l3, w2b + W2_HEAD + np * (16 * LD2 * 2));
            MMA16816(lvL[0], a20, l0, l1);
            MMA16816(lvH[0], a20, l2, l3);
            MMA16816(lvL[1], a21, l0, l1);
            MMA16816(lvH[1], a21, l2, l3);
        }

        __syncthreads();
        if (ch + 2 < NCH) {
            load_w1_chunk_async(sb, ch + 2, buf, tid);
            load_w2_chunk_async(sb, ch + 2, buf, tid);
            CP_COMMIT();
        }
    }

    // --- dump mu/lv to overlay (W1 region dead) ---
    __syncthreads();
    {
        float* sMu = (float*)(smem + SM_MU);
        float* sLv = (float*)(smem + SM_LV);
        int cc = (lane & 3) * 2;
        #pragma unroll
        for (int t = 0; t < 2; ++t) {
            int rr = warp * 32 + t * 16 + (lane >> 2);
            *(float2*)&sMu[rr * LDMU + cc]           = make_float2(muL[t][0], muL[t][1]);
            *(float2*)&sMu[(rr + 8) * LDMU + cc]     = make_float2(muL[t][2], muL[t][3]);
            *(float2*)&sMu[rr * LDMU + cc + 8]       = make_float2(muH[t][0], muH[t][1]);
            *(float2*)&sMu[(rr + 8) * LDMU + cc + 8] = make_float2(muH[t][2], muH[t][3]);
            *(float2*)&sLv[rr * LDMU + cc]           = make_float2(lvL[t][0], lvL[t][1]);
            *(float2*)&sLv[(rr + 8) * LDMU + cc]     = make_float2(lvL[t][2], lvL[t][3]);
            *(float2*)&sLv[rr * LDMU + cc + 8]       = make_float2(lvH[t][0], lvH[t][1]);
            *(float2*)&sLv[(rr + 8) * LDMU + cc + 8] = make_float2(lvH[t][2], lvH[t][3]);
        }
    }
    __syncthreads();

    // --- loss epilogue: each thread owns one row ---
    const float* sMu = (const float*)(smem + SM_MU);
    const float* sLv = (const float*)(smem + SM_LV);
    int gr = r0 + tid;
    const float4* a4 = (const float4*)(actions + (size_t)gr * A);
    const float4* p4 = (const float4*)(blp + (size_t)gr * A);
    float lsum = 0.f;
    #pragma unroll
    for (int q = 0; q < 4; ++q) {
        float4 av = a4[q];
        float4 bv = p4[q];
        float aarr[4] = {av.x, av.y, av.z, av.w};
        float barr[4] = {bv.x, bv.y, bv.z, bv.w};
        #pragma unroll
        for (int j = 0; j < 4; ++j) {
            int col = q * 4 + j;
            float mu = sMu[tid * LDMU + col] + sBias[col];
            float lv = sLv[tid * LDMU + col] + sBias[16 + col];
            float d  = aarr[j] - mu;
            float logp = -0.5f * d * d * __expf(-lv) - 0.5f * lv - LOG_SQRT_2PI;
            lsum += logp - barr[j];
        }
    }
    float ratio = __expf(lsum);
    float ahat  = (g_adv[gr] - g_mean) * g_inv;
    float rc    = fminf(fmaxf(ratio, 1.f - EPSC), 1.f + EPSC);
    float term  = fminf(ratio * ahat, rc * ahat);

    #pragma unroll
    for (int o = 16; o > 0; o >>= 1) term += __shfl_down_sync(0xffffffffu, term, o);
    if ((tid & 31) == 0) sRed[warp] = term;
    __syncthreads();
    if (tid == 0) {
        float bsum = sRed[0] + sRed[1] + sRed[2] + sRed[3];
        atomicAdd(&g_actor, bsum);
        __threadfence();
        uint done = atomicAdd(&g_cnt_main, 1u);
        if (done == (uint)(gridDim.x - 1)) {
            float actor = atomicAdd(&g_actor, 0.f);
            out[0] = g_critic - actor / (float)T;
        }
    }
}

// ---------------- launch ----------------
extern "C" void kernel_launch(void* const* d_in, const int* in_sizes, int n_in,
                              void* d_out, int out_size) {
    const float* states  = (const float*)d_in[0];
    const float* actions = (const float*)d_in[1];
    const float* rewards = (const float*)d_in[2];
    const float* values  = (const float*)d_in[3];
    const float* blp     = (const float*)d_in[4];
    const float* W1      = (const float*)d_in[5];
    const float* b1      = (const float*)d_in[6];
    const float* Wmu     = (const float*)d_in[7];
    const float* bmu     = (const float*)d_in[8];
    const float* Wlv     = (const float*)d_in[9];
    const float* blv     = (const float*)d_in[10];
    const int*   masks   = (const int*)d_in[11];

    cudaFuncSetAttribute(k_main, cudaFuncAttributeMaxDynamicSharedMemorySize, SM_TOTAL);

    k_prep<<<512, 256>>>(W1, Wmu, Wlv, b1);
    k_scan1<<<256, 256>>>(rewards, masks);
    k_scan3<<<256, 256>>>(rewards, masks, values);
    k_main<<<T / RT, 128, SM_TOTAL>>>(states, actions, blp, bmu, blv, (float*)d_out);
}